// round 17
// baseline (speedup 1.0000x reference)
#include <cuda_runtime.h>
#include <cuda_bf16.h>

#define THR 1.2f
#define WSCALE 524288.0f              // 2^19
#define INV_WSCALE (1.0f / 524288.0f)

// ---------------------------------------------------------------------------
// Device globals
// ---------------------------------------------------------------------------
__device__ unsigned g_mask[512 * 1024 * 2];          // [t*64+b][px] uint2 channel masks
__device__ float    g_part[256 * 10];                // per-block FC partials
__device__ __align__(16) signed char g_wq[3 * 9 * 64 * 64];  // [limb][pos][co][cin]
__device__ float    g_wfcT[65536 * 12];              // [co*1024+px][12] transposed wfc

__device__ __forceinline__ unsigned smem_u32(const void* p) {
    unsigned a;
    asm("{ .reg .u64 t; cvta.to.shared.u64 t, %1; cvt.u32.u64 %0, t; }"
        : "=r"(a) : "l"(p));
    return a;
}

#define LDMX4(r, addr) \
    asm volatile("ldmatrix.sync.aligned.m8n8.x4.shared.b16 {%0,%1,%2,%3}, [%4];" \
        : "=r"((r)[0]), "=r"((r)[1]), "=r"((r)[2]), "=r"((r)[3]) : "r"(addr))
#define MMAI16832(c, a, b0, b1) \
    asm volatile("mma.sync.aligned.m16n8k32.row.col.s32.s8.s8.s32 " \
        "{%0,%1,%2,%3}, {%4,%5,%6,%7}, {%8,%9}, {%0,%1,%2,%3};" \
        : "+r"((c)[0]), "+r"((c)[1]), "+r"((c)[2]), "+r"((c)[3]) \
        : "r"((a)[0]), "r"((a)[1]), "r"((a)[2]), "r"((a)[3]), "r"(b0), "r"(b1))

// packed f32x2 helpers for k1
#define PACK2(d, x)   asm("mov.b64 %0, {%1,%1};" : "=l"(d) : "f"(x))
#define PACKAB(d, a, b) asm("mov.b64 %0, {%1,%2};" : "=l"(d) : "f"(a), "f"(b))
#define FMA2(acc, w, x2) \
    asm("fma.rn.f32x2 %0, %1, %2, %0;" : "+l"(acc) : "l"(w), "l"(x2))
#define UNPACK2(lo, hi, v) \
    asm("mov.b64 {%0,%1}, %2;" : "=f"(lo), "=f"(hi) : "l"(v))

// ---------------------------------------------------------------------------
// Kernel 1: conv1 (3->64) + LIF -> channel bitmasks (unchanged)
// ---------------------------------------------------------------------------
__global__ __launch_bounds__(256) void k1_conv1(const float* __restrict__ x,
                                                const float* __restrict__ w1,
                                                const float* __restrict__ b1) {
    __shared__ float xs[3 * 34 * 36];
    __shared__ float ws[64 * 27];
    __shared__ float bs[64];

    const int tb  = blockIdx.x;
    const int tid = threadIdx.x;

    for (int i = tid; i < 64 * 27; i += 256) ws[i] = w1[i];
    if (tid < 64) bs[tid] = b1[tid];

    const float* xin = x + tb * 3 * 1024;
    for (int i = tid; i < 3 * 34 * 34; i += 256) {
        int cin = i / 1156, rem = i - cin * 1156;
        int yy = rem / 34, xx = rem - yy * 34;
        int gy = yy - 1, gx = xx - 1;
        float v = 0.f;
        if (gy >= 0 && gy < 32 && gx >= 0 && gx < 32)
            v = xin[cin * 1024 + gy * 32 + gx];
        xs[cin * 1224 + yy * 36 + xx] = v;
    }
    __syncthreads();

    const int wid  = tid >> 5;
    const int lane = tid & 31;

    unsigned long long wp[27];
#pragma unroll
    for (int k = 0; k < 27; k++)
        PACKAB(wp[k], ws[lane * 27 + k], ws[(lane + 32) * 27 + k]);
    unsigned long long bias2;
    PACKAB(bias2, bs[lane], bs[lane + 32]);

    for (int seg = wid; seg < 128; seg += 8) {
        const int y   = seg >> 2;
        const int xc0 = (seg & 3) * 8;

        unsigned long long acc2[8];
#pragma unroll
        for (int px = 0; px < 8; px++) acc2[px] = bias2;

#pragma unroll
        for (int cin = 0; cin < 3; cin++) {
            const float* base = xs + cin * 1224 + xc0;
#pragma unroll
            for (int dr = 0; dr < 3; dr++) {
                const float4* rp = (const float4*)(base + (y + dr) * 36);
                float4 f0 = rp[0], f1 = rp[1], f2 = rp[2];
                unsigned long long x2[10];
                PACK2(x2[0], f0.x); PACK2(x2[1], f0.y); PACK2(x2[2], f0.z); PACK2(x2[3], f0.w);
                PACK2(x2[4], f1.x); PACK2(x2[5], f1.y); PACK2(x2[6], f1.z); PACK2(x2[7], f1.w);
                PACK2(x2[8], f2.x); PACK2(x2[9], f2.y);
                const int wb = cin * 9 + dr * 3;
#pragma unroll
                for (int px = 0; px < 8; px++) {
                    FMA2(acc2[px], wp[wb],     x2[px]);
                    FMA2(acc2[px], wp[wb + 1], x2[px + 1]);
                    FMA2(acc2[px], wp[wb + 2], x2[px + 2]);
                }
            }
        }

#pragma unroll
        for (int px = 0; px < 8; px++) {
            float lo, hi;
            UNPACK2(lo, hi, acc2[px]);
            unsigned mlo = __ballot_sync(0xffffffffu, lo >= THR);
            unsigned mhi = __ballot_sync(0xffffffffu, hi >= THR);
            if (lane == 0)
                ((uint2*)g_mask)[tb * 1024 + seg * 8 + px] = make_uint2(mlo, mhi);
        }
    }
}

// ---------------------------------------------------------------------------
// Kernel 2a: quantize w2 into 3 signed-byte limbs, W = A*65536 + B*256 + C,
// W = round(w * 2^19).  Layout [limb][pos][co][cin].
// ---------------------------------------------------------------------------
__global__ void k2a_quant(const float* __restrict__ w2) {
    int i = blockIdx.x * 256 + threadIdx.x;
    if (i >= 36864) return;
    int co = i / 576, rest = i - co * 576;
    int cin = rest / 9, pos = rest - cin * 9;
    int W = __float2int_rn(w2[i] * WSCALE);
    int c8 = (int)(signed char)(W & 0xFF);
    int W1 = (W - c8) >> 8;
    int b8 = (int)(signed char)(W1 & 0xFF);
    int a8 = (W1 - b8) >> 8;
    int idx = pos * 4096 + co * 64 + cin;
    g_wq[idx]             = (signed char)a8;
    g_wq[36864 + idx]     = (signed char)b8;
    g_wq[2 * 36864 + idx] = (signed char)c8;
}

// ---------------------------------------------------------------------------
// Kernel 2b: transpose wfc -> [co*1024+px][12]
// ---------------------------------------------------------------------------
__global__ void k2b_transpose(const float* __restrict__ wfc) {
    int i = blockIdx.x * 256 + threadIdx.x;   // 0..65535
    float v[10];
#pragma unroll
    for (int o = 0; o < 10; o++) v[o] = wfc[o * 65536 + i];
    float4* dst = (float4*)(g_wfcT + i * 12);
    dst[0] = make_float4(v[0], v[1], v[2], v[3]);
    dst[1] = make_float4(v[4], v[5], v[6], v[7]);
    dst[2] = make_float4(v[8], v[9], 0.f, 0.f);
}

// ---------------------------------------------------------------------------
// Kernel 2: conv2 via int8 3-limb mma.sync (m16n8k32.s8) with shift-chained
// s32 accumulator + LIF + count over t + fused FC.
// Grid: (2 strips of 16 rows, 64 b) = 128 CTAs, 256 threads = 8 warps.
// Warp = 2 rows = 4 m16 tiles (R12 structure).
// Plane: s8 spikes, 612 rows x 64B, chunk swizzle j ^= ((row>>1)&3).
// Weights: [limb][pos] tables of 4096B; co-pair rows of 128B, chunk swizzle
// j ^= ((co>>1)&3)  (conflict-free for 8-row ldmatrix).
// SMEM: thr2[64] @0 | red @256 | LUT @1024 (2KB) | B @5120 (110592B)
//       plane @115712 (39168B) -> total 154880
// ---------------------------------------------------------------------------
#define OFF_RED   256
#define OFF_LUT   1024
#define OFF_B     5120
#define OFF_PLANE 115712
#define SMEM_K2   154880

__global__ __launch_bounds__(256, 1) void k2_mma(const float* __restrict__ b2) {
    extern __shared__ __align__(128) char sm[];
    const unsigned smb = smem_u32(sm);

    const int sy  = blockIdx.x;       // 16-row strip (0..1)
    const int b   = blockIdx.y;
    const int tid = threadIdx.x;
    const int wid = tid >> 5;
    const int lane = tid & 31;
    const int ry2 = wid * 2;          // first image row of this warp (0..14)

    // LUT: byte -> 8 s8 bytes (0/1), 8B per entry
    if (tid < 256) {
        int v = tid;
        unsigned lo = (v & 1) | (((v >> 1) & 1) << 8) |
                      (((v >> 2) & 1) << 16) | (((v >> 3) & 1) << 24);
        unsigned hi = ((v >> 4) & 1) | (((v >> 5) & 1) << 8) |
                      (((v >> 6) & 1) << 16) | (((v >> 7) & 1) << 24);
        *(uint2*)(sm + OFF_LUT + v * 8) = make_uint2(lo, hi);
    }
    if (tid < 64) ((float*)sm)[tid] = THR - b2[tid];

    // weights -> SMEM: co-pair 128B rows, chunk swizzle j ^= ((co>>1)&3)
    {
        const char* src = (const char*)g_wq;
        for (int i = tid; i < 6912; i += 256) {
            int off = i * 16;
            int inner = off & 4095;
            int co = inner >> 6;
            int j  = (inner >> 4) & 3;
            uint4 v = *(const uint4*)(src + off);
            *(uint4*)(sm + OFF_B + (off & ~4095) + ((co >> 1) << 7) +
                      ((co & 1) << 6) + (((j ^ ((co >> 1) & 3)) << 4))) = v;
        }
    }
    __syncthreads();

    const float* s_thr2 = (const float*)sm;

    // nibble-packed spike counters: cntp[tile][q], nf in nibbles (cnt<=8)
    unsigned cntp[4][4];
#pragma unroll
    for (int h = 0; h < 4; h++)
#pragma unroll
        for (int q = 0; q < 4; q++) cntp[h][q] = 0u;

    const uint2* gm = (const uint2*)g_mask;
    const unsigned p0 = smb + OFF_PLANE;

    // per-lane B addressing constants
    const int cobase = ((lane >> 4) << 3) + (lane & 7);   // co within n-pair
    const int bjh    = (lane >> 3) & 1;                   // 16B half of k32

    for (int t = 0; t < 8; t++) {
        // --- expand spike masks: 612 rows (18 image rows + x halo), s8
        for (int r = tid; r < 612; r += 256) {
            int iy = r / 34, ixp = r - iy * 34;
            int y = sy * 16 - 1 + iy;
            int ix = ixp - 1;
            uint2 m = make_uint2(0u, 0u);
            if ((unsigned)y < 32u && (unsigned)ix < 32u)
                m = gm[(t * 64 + b) * 1024 + y * 32 + ix];
            char* pb = sm + OFF_PLANE + r * 64;
            const int rs = (r >> 1) & 3;
#pragma unroll
            for (int k = 0; k < 4; k++) {
                unsigned bits16 = (k < 2) ? (m.x >> (16 * k))
                                          : (m.y >> (16 * (k - 2)));
                uint2 e0 = *(const uint2*)(sm + OFF_LUT + (bits16 & 0xFFu) * 8);
                uint2 e1 = *(const uint2*)(sm + OFF_LUT + ((bits16 >> 8) & 0xFFu) * 8);
                *(uint4*)(pb + ((k ^ rs) << 4)) = make_uint4(e0.x, e0.y, e1.x, e1.y);
            }
        }
        __syncthreads();

        int c[4][8][4];   // [tile][nf][q] shift-chained s32 accumulators
#pragma unroll
        for (int h = 0; h < 4; h++)
#pragma unroll
            for (int nf = 0; nf < 8; nf++)
#pragma unroll
                for (int q = 0; q < 4; q++) c[h][nf][q] = 0;

#pragma unroll 1
        for (int limb = 0; limb < 3; limb++) {
            if (limb > 0) {
#pragma unroll
                for (int h = 0; h < 4; h++)
#pragma unroll
                    for (int nf = 0; nf < 8; nf++)
#pragma unroll
                        for (int q = 0; q < 4; q++) c[h][nf][q] <<= 8;
            }
#pragma unroll 1
            for (int pos = 0; pos < 9; pos++) {
                const int dy = pos / 3, dx = pos - dy * 3;
                const int prbase = (ry2 + dy) * 34 + dx + (lane & 15);
                const unsigned wtab = smb + OFF_B + (limb * 9 + pos) * 4096;
#pragma unroll
                for (int kt = 0; kt < 2; kt++) {
                    unsigned a[4][4];
#pragma unroll
                    for (int h = 0; h < 4; h++) {
                        const int prb = prbase + (h >> 1) * 34 + (h & 1) * 16;
                        const unsigned j = (unsigned)(kt * 2 + (lane >> 4));
                        LDMX4(a[h], p0 + prb * 64 + ((j ^ ((prb >> 1) & 3)) << 4));
                    }
                    const unsigned bj = (unsigned)(kt * 2 + bjh);
#pragma unroll
                    for (int ntp = 0; ntp < 4; ntp++) {
                        const int co = ntp * 16 + cobase;
                        unsigned bb[4];
                        LDMX4(bb, wtab + ((co >> 1) << 7) + ((co & 1) << 6) +
                                   (((bj ^ ((co >> 1) & 3)) << 4)));
#pragma unroll
                        for (int h = 0; h < 4; h++) {
                            MMAI16832(c[h][ntp * 2],     a[h], bb[0], bb[1]);
                            MMAI16832(c[h][ntp * 2 + 1], a[h], bb[2], bb[3]);
                        }
                    }
                }
            }
        }

        // threshold -> nibble-packed spike counts
#pragma unroll
        for (int h = 0; h < 4; h++)
#pragma unroll
            for (int nf = 0; nf < 8; nf++)
#pragma unroll
                for (int q = 0; q < 4; q++) {
                    const int co = nf * 8 + (lane & 3) * 2 + (q & 1);
                    const float v = (float)c[h][nf][q] * INV_WSCALE;
                    cntp[h][q] += (v >= s_thr2[co]) ? (1u << (4 * nf)) : 0u;
                }

        __syncthreads();   // MMA reads done before next t overwrites plane
    }

    // --- fused FC fold
    float oa[10];
#pragma unroll
    for (int o = 0; o < 10; o++) oa[o] = 0.f;
#pragma unroll
    for (int h = 0; h < 4; h++) {
        const int gpbase = (sy * 16 + ry2 + (h >> 1)) * 32 + (h & 1) * 16;
#pragma unroll
        for (int q = 0; q < 4; q++) {
            const int gp = gpbase + (lane >> 2) + ((q >> 1) << 3);
#pragma unroll
            for (int nf = 0; nf < 8; nf++) {
                const int co = nf * 8 + (lane & 3) * 2 + (q & 1);
                const float4* p = (const float4*)(g_wfcT + (co * 1024 + gp) * 12);
                float4 f0 = p[0], f1 = p[1], f2 = p[2];
                const float cc = (float)((cntp[h][q] >> (4 * nf)) & 0xFu);
                oa[0] += cc * f0.x; oa[1] += cc * f0.y; oa[2] += cc * f0.z; oa[3] += cc * f0.w;
                oa[4] += cc * f1.x; oa[5] += cc * f1.y; oa[6] += cc * f1.z; oa[7] += cc * f1.w;
                oa[8] += cc * f2.x; oa[9] += cc * f2.y;
            }
        }
    }

    float* red = (float*)(sm + OFF_RED);
#pragma unroll
    for (int o = 0; o < 10; o++) {
        float v = oa[o];
        v += __shfl_down_sync(0xffffffffu, v, 16);
        v += __shfl_down_sync(0xffffffffu, v, 8);
        v += __shfl_down_sync(0xffffffffu, v, 4);
        v += __shfl_down_sync(0xffffffffu, v, 2);
        v += __shfl_down_sync(0xffffffffu, v, 1);
        if (lane == 0) red[wid * 10 + o] = v;
    }
    __syncthreads();
    if (tid < 10) {
        float s = 0.f;
#pragma unroll
        for (int w = 0; w < 8; w++) s += red[w * 10 + tid];
        g_part[(b * 2 + sy) * 10 + tid] = s;
    }
}

// ---------------------------------------------------------------------------
// Kernel 3: final reduction
// ---------------------------------------------------------------------------
__global__ void k3_final(const float* __restrict__ bfc, float* __restrict__ out) {
    const int tid = threadIdx.x;
    if (tid < 640) {
        const int b = tid / 10, o = tid - b * 10;
        float s = 8.f * bfc[o];
#pragma unroll
        for (int k = 0; k < 2; k++) s += g_part[(b * 2 + k) * 10 + o];
        out[tid] = s;
    }
}

extern "C" void kernel_launch(void* const* d_in, const int* in_sizes, int n_in,
                              void* d_out, int out_size) {
    const float* x   = (const float*)d_in[0];  // [8,64,3,32,32]
    const float* w1  = (const float*)d_in[1];  // [64,3,3,3]
    const float* b1  = (const float*)d_in[2];  // [64]
    const float* w2  = (const float*)d_in[3];  // [64,64,3,3]
    const float* b2  = (const float*)d_in[4];  // [64]
    const float* wfc = (const float*)d_in[5];  // [10, 65536]
    const float* bfc = (const float*)d_in[6];  // [10]
    float* out = (float*)d_out;                // [64,10]

    cudaFuncSetAttribute(k2_mma, cudaFuncAttributeMaxDynamicSharedMemorySize,
                         SMEM_K2);

    k1_conv1<<<512, 256>>>(x, w1, b1);
    k2a_quant<<<144, 256>>>(w2);
    k2b_transpose<<<256, 256>>>(wfc);
    k2_mma<<<dim3(2, 64), 256, SMEM_K2>>>(b2);
    k3_final<<<1, 640>>>(bfc, out);
}